// round 4
// baseline (speedup 1.0000x reference)
#include <cuda_runtime.h>
#include <cstddef>

#define N_STEPS 4096
#define NU 8
#define R 256
#define NX 64
#define NY 8
#define L 16
#define C_CHUNKS (N_STEPS / L)   // 256
#define QTOT (NU * L)            // 128
#define RSUB 2

typedef unsigned long long ull;

// Scratch (device globals: no allocation allowed in kernel_launch)
__device__ float g_KcatT[QTOT * NX];            // [q][i], q=(t*NU+j) holds (A^{L-1-t}B)^T
__device__ float g_AL[NX * NX];                 // A^L row-major
__device__ float g_W[NX * QTOT];                // K-stack workspace [i][s*NU+j]
__device__ float g_Pfin[C_CHUNKS * NX * R];
__device__ float g_Xstart[C_CHUNKS * NX * R];

// ---------------- packed f32x2 helpers ----------------
__device__ __forceinline__ ull pack2(float lo, float hi) {
    ull v; asm("mov.b64 %0,{%1,%2};" : "=l"(v) : "f"(lo), "f"(hi)); return v;
}
__device__ __forceinline__ void unpack2(ull v, float& lo, float& hi) {
    asm("mov.b64 {%0,%1},%2;" : "=f"(lo), "=f"(hi) : "l"(v));
}
__device__ __forceinline__ ull fma2(ull a, ull b, ull c) {
    ull d; asm("fma.rn.f32x2 %0,%1,%2,%3;" : "=l"(d) : "l"(a), "l"(b), "l"(c)); return d;
}

// ---------------------------------------------------------------------------
// Kernel 0: precompute K[s]=A^s B (s=0..L-1) by DOUBLING (4 rounds), and A^L.
// Round m: W[:, w..2w) = A^(2^m) * W[:, 0..w) ; then square P. 512 threads.
// ---------------------------------------------------------------------------
__global__ void k_precompute(const float* __restrict__ A, const float* __restrict__ B) {
    __shared__ float sP[NX * NX];
    __shared__ float sQ[NX * NX];
    const int t = threadIdx.x;  // 512

    for (int idx = t; idx < NX * NX; idx += 512) sP[idx] = A[idx];
    for (int idx = t; idx < NX * NU; idx += 512) {
        int i = idx / NU, j = idx % NU;
        g_W[i * QTOT + j] = B[idx];
    }
    __syncthreads();

    float* p = sP;
    float* q = sQ;
    int wcols = NU;  // 8 -> 16 -> 32 -> 64 -> 128
    for (int m = 0; m < 4; m++) {
        // append: g_W[:, wcols..2wcols) = p @ g_W[:, 0..wcols)
        for (int idx = t; idx < NX * wcols; idx += 512) {
            int i = idx / wcols, jc = idx % wcols;
            float a0 = 0.f, a1 = 0.f, a2 = 0.f, a3 = 0.f;
            #pragma unroll 4
            for (int k = 0; k < NX; k += 4) {
                a0 += p[i * NX + k + 0] * g_W[(k + 0) * QTOT + jc];
                a1 += p[i * NX + k + 1] * g_W[(k + 1) * QTOT + jc];
                a2 += p[i * NX + k + 2] * g_W[(k + 2) * QTOT + jc];
                a3 += p[i * NX + k + 3] * g_W[(k + 3) * QTOT + jc];
            }
            g_W[i * QTOT + wcols + jc] = (a0 + a1) + (a2 + a3);
        }
        // square p -> q (reads only p; no conflict with append)
        for (int idx = t; idx < NX * NX; idx += 512) {
            int i = idx >> 6, j = idx & 63;
            float a0 = 0.f, a1 = 0.f, a2 = 0.f, a3 = 0.f;
            #pragma unroll 4
            for (int k = 0; k < NX; k += 4) {
                a0 += p[i * NX + k + 0] * p[(k + 0) * NX + j];
                a1 += p[i * NX + k + 1] * p[(k + 1) * NX + j];
                a2 += p[i * NX + k + 2] * p[(k + 2) * NX + j];
                a3 += p[i * NX + k + 3] * p[(k + 3) * NX + j];
            }
            q[idx] = (a0 + a1) + (a2 + a3);
        }
        __syncthreads();
        float* tmp = p; p = q; q = tmp;
        wcols *= 2;
    }
    // p = A^16, g_W complete (16 K-blocks)
    for (int idx = t; idx < NX * NX; idx += 512) g_AL[idx] = p[idx];
    // scatter time-flipped transpose: KcatT[((L-1-s)*NU+j)*NX + i] = W[i][s*NU+j]
    for (int idx = t; idx < NX * QTOT; idx += 512) {
        int i = idx >> 7, col = idx & 127;
        int s = col >> 3, j = col & 7;
        g_KcatT[(((L - 1 - s) * NU + j) * NX) + i] = g_W[idx];
    }
}

// ---------------------------------------------------------------------------
// Kernel 1: Pfin[c] = Kcat(64 x 128) @ Uc(128 x 256), packed f32x2 accumulators.
// ---------------------------------------------------------------------------
__global__ void k_phase1(const float* __restrict__ u) {
    __shared__ __align__(16) float sU[64 * 64];
    __shared__ __align__(16) float sKT[64 * 64];
    const int c = blockIdx.x;
    const int r0 = blockIdx.y * 64;
    const int t = threadIdx.x;
    const int r = t & 63;
    const int ig = t >> 6;

    ull acc2[8];
    #pragma unroll
    for (int m = 0; m < 8; m++) acc2[m] = pack2(0.f, 0.f);

    const float* Uc = u + (size_t)c * L * NU * R;

    for (int qb = 0; qb < QTOT / 64; qb++) {
        __syncthreads();
        #pragma unroll
        for (int m = 0; m < 16; m++) {
            int qq = m * 4 + ig;
            sU[qq * 64 + r] = Uc[(size_t)(qb * 64 + qq) * R + r0 + r];
        }
        for (int idx = t; idx < 4096; idx += 256)
            sKT[idx] = g_KcatT[qb * 64 * 64 + idx];
        __syncthreads();

        #pragma unroll 8
        for (int qq = 0; qq < 64; qq++) {
            float uval = sU[qq * 64 + r];
            ull uv = pack2(uval, uval);
            const ulonglong2* k2p = (const ulonglong2*)(sKT + qq * 64 + ig * 16);
            #pragma unroll
            for (int m2 = 0; m2 < 4; m2++) {
                ulonglong2 kk = k2p[m2];
                acc2[2 * m2 + 0] = fma2(kk.x, uv, acc2[2 * m2 + 0]);
                acc2[2 * m2 + 1] = fma2(kk.y, uv, acc2[2 * m2 + 1]);
            }
        }
    }
    #pragma unroll
    for (int m = 0; m < 8; m++) {
        float lo, hi; unpack2(acc2[m], lo, hi);
        int i = ig * 16 + 2 * m;
        g_Pfin[((size_t)c * NX + i) * R + r0 + r]     = lo;
        g_Pfin[((size_t)c * NX + i + 1) * R + r0 + r] = hi;
    }
}

// ---------------------------------------------------------------------------
// Kernel 2: boundary scan (256 iters), double-buffered (one sync per iter).
// ---------------------------------------------------------------------------
__global__ void k_phase2(const float* __restrict__ x0) {
    __shared__ __align__(16) float sAL[NX * NX];
    __shared__ float sx[2][NX * RSUB];
    const int t = threadIdx.x;  // 128
    const int r = t & (RSUB - 1);
    const int i = t / RSUB;
    const int rg = blockIdx.x * RSUB + r;

    for (int idx = t; idx < NX * NX; idx += NX * RSUB) sAL[idx] = g_AL[idx];
    float xi = x0[i * R + rg];
    sx[0][i * RSUB + r] = xi;
    __syncthreads();

    int p = 0;
    float pf = g_Pfin[(size_t)i * R + rg];
    for (int c = 0; c < C_CHUNKS; c++) {
        g_Xstart[((size_t)c * NX + i) * R + rg] = xi;
        float pf_next = (c + 1 < C_CHUNKS)
            ? g_Pfin[((size_t)(c + 1) * NX + i) * R + rg] : 0.f;
        float a0 = 0.f, a1 = 0.f, a2 = 0.f, a3 = 0.f;
        const float4* a4 = (const float4*)(sAL + i * NX);
        #pragma unroll
        for (int jb = 0; jb < NX / 4; jb++) {
            float4 a = a4[jb];
            a0 += a.x * sx[p][(jb * 4 + 0) * RSUB + r];
            a1 += a.y * sx[p][(jb * 4 + 1) * RSUB + r];
            a2 += a.z * sx[p][(jb * 4 + 2) * RSUB + r];
            a3 += a.w * sx[p][(jb * 4 + 3) * RSUB + r];
        }
        xi = ((a0 + a1) + (a2 + a3)) + pf;
        sx[p ^ 1][i * RSUB + r] = xi;
        pf = pf_next;
        __syncthreads();
        p ^= 1;
    }
}

// ---------------------------------------------------------------------------
// Kernel 3 (v4): full column per thread; ONLY acc2[32] register-resident.
// x_k lives in a private smem scratch column (stride 65, conflict-free);
// Y[k] and X[k] are produced from acc2 (== x_k) at the TOP of each step,
// then acc2 is rebuilt as B u + A x. No shuffles, no per-step syncs.
// Grid (C_CHUNKS, R/64), 64 threads (2 warps).
// ---------------------------------------------------------------------------
__global__ void __launch_bounds__(64) k_phase3(
    const float* __restrict__ u, const float* __restrict__ A,
    const float* __restrict__ B, const float* __restrict__ Cy,
    const float* __restrict__ D,
    float* __restrict__ outY, float* __restrict__ outX)
{
    __shared__ __align__(16) ull sA2[64 * 32];  // [j][i2] = {A[2i2][j], A[2i2+1][j]}
    __shared__ __align__(16) ull sB2[NU * 32];
    __shared__ __align__(16) ull sC2[NY * 32];  // [o][j2] = {C[o][2j2], C[o][2j2+1]}
    __shared__ float sD[NY * NU];
    __shared__ float xbuf[64 * 65];             // private scratch: [tid][65]

    const int tid = threadIdx.x;                // 64
    const int c = blockIdx.x;
    const int r = blockIdx.y * 64 + tid;

    for (int idx = tid; idx < 64 * 32; idx += 64) {
        int j = idx >> 5, i2 = idx & 31;
        sA2[idx] = pack2(A[(2 * i2) * NX + j], A[(2 * i2 + 1) * NX + j]);
    }
    for (int idx = tid; idx < NU * 32; idx += 64) {
        int j = idx >> 5, i2 = idx & 31;
        sB2[idx] = pack2(B[(2 * i2) * NU + j], B[(2 * i2 + 1) * NU + j]);
    }
    for (int idx = tid; idx < NY * 32; idx += 64) {
        int o = idx >> 5, j2 = idx & 31;
        sC2[idx] = pack2(Cy[o * NX + 2 * j2], Cy[o * NX + 2 * j2 + 1]);
    }
    if (tid == 0) {
        #pragma unroll
        for (int idx = 0; idx < NY * NU; idx++) sD[idx] = D[idx];
    }

    // acc2 <- starting state x_0 of this chunk (packed row pairs)
    ull acc2[32];
    {
        const float* xs = g_Xstart + (size_t)c * NX * R + r;
        #pragma unroll
        for (int k = 0; k < 32; k++)
            acc2[k] = pack2(xs[(size_t)(2 * k) * R], xs[(size_t)(2 * k + 1) * R]);
    }
    __syncthreads();

    float* xcol = xbuf + tid * 65;
    const float* up = u    + (size_t)c * L * NU * R + r;
    float*       yp = outY + (size_t)c * L * NY * R + r;
    float*       xp = outX + (size_t)c * L * NX * R + r;

    #pragma unroll 1
    for (int step = 0; step < L; step++) {
        // ---- inputs ----
        float uu[NU];
        #pragma unroll
        for (int j = 0; j < NU; j++) uu[j] = up[(size_t)j * R];

        // ---- Y[k] = C x_k + D u_k, with x_k = acc2 ----
        #pragma unroll 2
        for (int o = 0; o < NY; o++) {
            ull ya = pack2(0.f, 0.f);
            const ulonglong2* c2 = (const ulonglong2*)(sC2 + o * 32);
            #pragma unroll
            for (int k2 = 0; k2 < 16; k2++) {
                ulonglong2 cc = c2[k2];
                ya = fma2(cc.x, acc2[2 * k2 + 0], ya);
                ya = fma2(cc.y, acc2[2 * k2 + 1], ya);
            }
            float lo, hi; unpack2(ya, lo, hi);
            float ds = 0.f;
            #pragma unroll
            for (int j = 0; j < NU; j++) ds += sD[o * NU + j] * uu[j];
            yp[(size_t)o * R] = (lo + hi) + ds;
        }

        // ---- store X[k] to gmem AND to private smem scratch ----
        #pragma unroll
        for (int k = 0; k < 32; k++) {
            float lo, hi; unpack2(acc2[k], lo, hi);
            xp[(size_t)(2 * k) * R]     = lo;
            xp[(size_t)(2 * k + 1) * R] = hi;
            xcol[2 * k]     = lo;
            xcol[2 * k + 1] = hi;
        }

        // ---- acc2 = B u (overwrites; x_k is safe in xcol) ----
        {
            ull uv0 = pack2(uu[0], uu[0]);
            const ulonglong2* b0 = (const ulonglong2*)(sB2);
            #pragma unroll
            for (int k2 = 0; k2 < 16; k2++) {
                ulonglong2 bb = b0[k2];
                acc2[2 * k2 + 0] = fma2(bb.x, uv0, pack2(0.f, 0.f));
                acc2[2 * k2 + 1] = fma2(bb.y, uv0, pack2(0.f, 0.f));
            }
            #pragma unroll 1
            for (int j = 1; j < NU; j++) {
                ull uvj = pack2(uu[j], uu[j]);
                const ulonglong2* bj = (const ulonglong2*)(sB2 + j * 32);
                #pragma unroll
                for (int k2 = 0; k2 < 16; k2++) {
                    ulonglong2 bb = bj[k2];
                    acc2[2 * k2 + 0] = fma2(bb.x, uvj, acc2[2 * k2 + 0]);
                    acc2[2 * k2 + 1] = fma2(bb.y, uvj, acc2[2 * k2 + 1]);
                }
            }
        }

        // ---- acc2 += A x_k (x from private scratch; uniform A broadcasts) ----
        #pragma unroll 2
        for (int j = 0; j < NX; j++) {
            float xj = xcol[j];
            ull sj = pack2(xj, xj);
            const ulonglong2* Aj = (const ulonglong2*)(sA2 + j * 32);
            #pragma unroll
            for (int k2 = 0; k2 < 16; k2++) {
                ulonglong2 aa = Aj[k2];
                acc2[2 * k2 + 0] = fma2(aa.x, sj, acc2[2 * k2 + 0]);
                acc2[2 * k2 + 1] = fma2(aa.y, sj, acc2[2 * k2 + 1]);
            }
        }

        up += (size_t)NU * R;
        yp += (size_t)NY * R;
        xp += (size_t)NX * R;
    }
}

// ---------------------------------------------------------------------------
extern "C" void kernel_launch(void* const* d_in, const int* in_sizes, int n_in,
                              void* d_out, int out_size) {
    const float* u  = (const float*)d_in[0];
    const float* x0 = (const float*)d_in[1];
    const float* A  = (const float*)d_in[2];
    const float* B  = (const float*)d_in[3];
    const float* Cy = (const float*)d_in[4];
    const float* D  = (const float*)d_in[5];
    float* outY = (float*)d_out;
    float* outX = (float*)d_out + (size_t)N_STEPS * NY * R;

    k_precompute<<<1, 512>>>(A, B);
    k_phase1<<<dim3(C_CHUNKS, R / 64), 256>>>(u);
    k_phase2<<<R / RSUB, NX * RSUB>>>(x0);
    k_phase3<<<dim3(C_CHUNKS, R / 64), 64>>>(u, A, B, Cy, D, outY, outX);
}

// round 5
// speedup vs baseline: 1.1095x; 1.1095x over previous
#include <cuda_runtime.h>
#include <cstddef>

#define N_STEPS 4096
#define NU 8
#define R 256
#define NX 64
#define NY 8
#define L 16
#define C_CHUNKS (N_STEPS / L)   // 256
#define QTOT (NU * L)            // 128
#define RSUB 2

typedef unsigned long long ull;

// Scratch (device globals: no allocation allowed in kernel_launch)
__device__ float g_KcatT[QTOT * NX];            // [q][i], q=(t*NU+j) holds (A^{L-1-t}B)^T
__device__ float g_AL[NX * NX];                 // A^L row-major
__device__ float g_W[NX * QTOT];                // K-stack workspace [i][s*NU+j]
__device__ float g_Pfin[C_CHUNKS * NX * R];
__device__ float g_Xstart[C_CHUNKS * NX * R];

// ---------------- packed f32x2 helpers ----------------
__device__ __forceinline__ ull pack2(float lo, float hi) {
    ull v; asm("mov.b64 %0,{%1,%2};" : "=l"(v) : "f"(lo), "f"(hi)); return v;
}
__device__ __forceinline__ void unpack2(ull v, float& lo, float& hi) {
    asm("mov.b64 {%0,%1},%2;" : "=f"(lo), "=f"(hi) : "l"(v));
}
__device__ __forceinline__ ull fma2(ull a, ull b, ull c) {
    ull d; asm("fma.rn.f32x2 %0,%1,%2,%3;" : "=l"(d) : "l"(a), "l"(b), "l"(c)); return d;
}

// ---------------------------------------------------------------------------
// Kernel 0: precompute K[s]=A^s B (s=0..L-1) by DOUBLING (4 rounds), and A^L.
// ---------------------------------------------------------------------------
__global__ void k_precompute(const float* __restrict__ A, const float* __restrict__ B) {
    __shared__ float sP[NX * NX];
    __shared__ float sQ[NX * NX];
    const int t = threadIdx.x;  // 512

    for (int idx = t; idx < NX * NX; idx += 512) sP[idx] = A[idx];
    for (int idx = t; idx < NX * NU; idx += 512) {
        int i = idx / NU, j = idx % NU;
        g_W[i * QTOT + j] = B[idx];
    }
    __syncthreads();

    float* p = sP;
    float* q = sQ;
    int wcols = NU;  // 8 -> 16 -> 32 -> 64 -> 128
    for (int m = 0; m < 4; m++) {
        for (int idx = t; idx < NX * wcols; idx += 512) {
            int i = idx / wcols, jc = idx % wcols;
            float a0 = 0.f, a1 = 0.f, a2 = 0.f, a3 = 0.f;
            #pragma unroll 4
            for (int k = 0; k < NX; k += 4) {
                a0 += p[i * NX + k + 0] * g_W[(k + 0) * QTOT + jc];
                a1 += p[i * NX + k + 1] * g_W[(k + 1) * QTOT + jc];
                a2 += p[i * NX + k + 2] * g_W[(k + 2) * QTOT + jc];
                a3 += p[i * NX + k + 3] * g_W[(k + 3) * QTOT + jc];
            }
            g_W[i * QTOT + wcols + jc] = (a0 + a1) + (a2 + a3);
        }
        for (int idx = t; idx < NX * NX; idx += 512) {
            int i = idx >> 6, j = idx & 63;
            float a0 = 0.f, a1 = 0.f, a2 = 0.f, a3 = 0.f;
            #pragma unroll 4
            for (int k = 0; k < NX; k += 4) {
                a0 += p[i * NX + k + 0] * p[(k + 0) * NX + j];
                a1 += p[i * NX + k + 1] * p[(k + 1) * NX + j];
                a2 += p[i * NX + k + 2] * p[(k + 2) * NX + j];
                a3 += p[i * NX + k + 3] * p[(k + 3) * NX + j];
            }
            q[idx] = (a0 + a1) + (a2 + a3);
        }
        __syncthreads();
        float* tmp = p; p = q; q = tmp;
        wcols *= 2;
    }
    for (int idx = t; idx < NX * NX; idx += 512) g_AL[idx] = p[idx];
    for (int idx = t; idx < NX * QTOT; idx += 512) {
        int i = idx >> 7, col = idx & 127;
        int s = col >> 3, j = col & 7;
        g_KcatT[(((L - 1 - s) * NU + j) * NX) + i] = g_W[idx];
    }
}

// ---------------------------------------------------------------------------
// Kernel 1: Pfin[c] = Kcat(64 x 128) @ Uc(128 x 256), packed f32x2.
// ---------------------------------------------------------------------------
__global__ void k_phase1(const float* __restrict__ u) {
    __shared__ __align__(16) float sU[64 * 64];
    __shared__ __align__(16) float sKT[64 * 64];
    const int c = blockIdx.x;
    const int r0 = blockIdx.y * 64;
    const int t = threadIdx.x;
    const int r = t & 63;
    const int ig = t >> 6;

    ull acc2[8];
    #pragma unroll
    for (int m = 0; m < 8; m++) acc2[m] = pack2(0.f, 0.f);

    const float* Uc = u + (size_t)c * L * NU * R;

    for (int qb = 0; qb < QTOT / 64; qb++) {
        __syncthreads();
        #pragma unroll
        for (int m = 0; m < 16; m++) {
            int qq = m * 4 + ig;
            sU[qq * 64 + r] = Uc[(size_t)(qb * 64 + qq) * R + r0 + r];
        }
        for (int idx = t; idx < 4096; idx += 256)
            sKT[idx] = g_KcatT[qb * 64 * 64 + idx];
        __syncthreads();

        #pragma unroll 8
        for (int qq = 0; qq < 64; qq++) {
            float uval = sU[qq * 64 + r];
            ull uv = pack2(uval, uval);
            const ulonglong2* k2p = (const ulonglong2*)(sKT + qq * 64 + ig * 16);
            #pragma unroll
            for (int m2 = 0; m2 < 4; m2++) {
                ulonglong2 kk = k2p[m2];
                acc2[2 * m2 + 0] = fma2(kk.x, uv, acc2[2 * m2 + 0]);
                acc2[2 * m2 + 1] = fma2(kk.y, uv, acc2[2 * m2 + 1]);
            }
        }
    }
    #pragma unroll
    for (int m = 0; m < 8; m++) {
        float lo, hi; unpack2(acc2[m], lo, hi);
        int i = ig * 16 + 2 * m;
        g_Pfin[((size_t)c * NX + i) * R + r0 + r]     = lo;
        g_Pfin[((size_t)c * NX + i + 1) * R + r0 + r] = hi;
    }
}

// ---------------------------------------------------------------------------
// Kernel 2: boundary scan (256 iters), double-buffered.
// ---------------------------------------------------------------------------
__global__ void k_phase2(const float* __restrict__ x0) {
    __shared__ __align__(16) float sAL[NX * NX];
    __shared__ float sx[2][NX * RSUB];
    const int t = threadIdx.x;  // 128
    const int r = t & (RSUB - 1);
    const int i = t / RSUB;
    const int rg = blockIdx.x * RSUB + r;

    for (int idx = t; idx < NX * NX; idx += NX * RSUB) sAL[idx] = g_AL[idx];
    float xi = x0[i * R + rg];
    sx[0][i * RSUB + r] = xi;
    __syncthreads();

    int p = 0;
    float pf = g_Pfin[(size_t)i * R + rg];
    for (int c = 0; c < C_CHUNKS; c++) {
        g_Xstart[((size_t)c * NX + i) * R + rg] = xi;
        float pf_next = (c + 1 < C_CHUNKS)
            ? g_Pfin[((size_t)(c + 1) * NX + i) * R + rg] : 0.f;
        float a0 = 0.f, a1 = 0.f, a2 = 0.f, a3 = 0.f;
        const float4* a4 = (const float4*)(sAL + i * NX);
        #pragma unroll
        for (int jb = 0; jb < NX / 4; jb++) {
            float4 a = a4[jb];
            a0 += a.x * sx[p][(jb * 4 + 0) * RSUB + r];
            a1 += a.y * sx[p][(jb * 4 + 1) * RSUB + r];
            a2 += a.z * sx[p][(jb * 4 + 2) * RSUB + r];
            a3 += a.w * sx[p][(jb * 4 + 3) * RSUB + r];
        }
        xi = ((a0 + a1) + (a2 + a3)) + pf;
        sx[p ^ 1][i * RSUB + r] = xi;
        pf = pf_next;
        __syncthreads();
        p ^= 1;
    }
}

// ---------------------------------------------------------------------------
// Kernel 3 (v5): TWO columns per thread, packed f32x2, x_k in packed LDS.64
// scratch. Every uniform A-load feeds 4 fma2. 64 threads (2 warps),
// grid (C_CHUNKS, 2). Dynamic smem (52.3 KB).
// ---------------------------------------------------------------------------
extern __shared__ __align__(16) char dsmem[];

__global__ void __launch_bounds__(64) k_phase3(
    const float* __restrict__ u, const float* __restrict__ A,
    const float* __restrict__ B, const float* __restrict__ Cy,
    const float* __restrict__ D,
    float* __restrict__ outY, float* __restrict__ outX)
{
    ull*   xs  = (ull*)dsmem;                       // [32][128] packed x pairs
    ull*   sA2 = (ull*)(dsmem + 32768);             // [j][i2] 64x32
    ull*   sB2 = (ull*)(dsmem + 32768 + 16384);     // [j][i2] 8x32
    ull*   sC2 = (ull*)(dsmem + 32768 + 16384 + 2048); // [o][j2] 8x32
    float* sD  = (float*)(dsmem + 32768 + 16384 + 4096);

    const int tid = threadIdx.x;                    // 64
    const int c = blockIdx.x;
    const int rA = blockIdx.y * 128 + tid;          // column a
    const int rB = rA + 64;                         // column b

    for (int idx = tid; idx < 64 * 32; idx += 64) {
        int j = idx >> 5, i2 = idx & 31;
        sA2[idx] = pack2(A[(2 * i2) * NX + j], A[(2 * i2 + 1) * NX + j]);
    }
    for (int idx = tid; idx < NU * 32; idx += 64) {
        int j = idx >> 5, i2 = idx & 31;
        sB2[idx] = pack2(B[(2 * i2) * NU + j], B[(2 * i2 + 1) * NU + j]);
    }
    for (int idx = tid; idx < NY * 32; idx += 64) {
        int o = idx >> 5, j2 = idx & 31;
        sC2[idx] = pack2(Cy[o * NX + 2 * j2], Cy[o * NX + 2 * j2 + 1]);
    }
    if (tid < NY * NU) sD[tid] = D[tid];

    // acc <- starting state of this chunk for both columns
    ull acc2a[32], acc2b[32];
    {
        const float* xsa = g_Xstart + (size_t)c * NX * R + rA;
        const float* xsb = g_Xstart + (size_t)c * NX * R + rB;
        #pragma unroll
        for (int k = 0; k < 32; k++) {
            acc2a[k] = pack2(xsa[(size_t)(2 * k) * R], xsa[(size_t)(2 * k + 1) * R]);
            acc2b[k] = pack2(xsb[(size_t)(2 * k) * R], xsb[(size_t)(2 * k + 1) * R]);
        }
    }
    __syncthreads();

    const float* upa = u    + (size_t)c * L * NU * R + rA;
    float*       ypa = outY + (size_t)c * L * NY * R + rA;
    float*       xpa = outX + (size_t)c * L * NX * R + rA;

    #pragma unroll 1
    for (int step = 0; step < L; step++) {
        // ---- inputs (both columns) ----
        float ua[NU], ub[NU];
        #pragma unroll
        for (int j = 0; j < NU; j++) {
            ua[j] = upa[(size_t)j * R];
            ub[j] = upa[(size_t)j * R + 64];
        }

        // ---- Y[k] = C x_k + D u_k for both columns (x_k = acc) ----
        #pragma unroll 2
        for (int o = 0; o < NY; o++) {
            ull ya = pack2(0.f, 0.f);
            ull yb = pack2(0.f, 0.f);
            const ulonglong2* c2 = (const ulonglong2*)(sC2 + o * 32);
            #pragma unroll
            for (int k2 = 0; k2 < 16; k2++) {
                ulonglong2 cc = c2[k2];
                ya = fma2(cc.x, acc2a[2 * k2 + 0], ya);
                ya = fma2(cc.y, acc2a[2 * k2 + 1], ya);
                yb = fma2(cc.x, acc2b[2 * k2 + 0], yb);
                yb = fma2(cc.y, acc2b[2 * k2 + 1], yb);
            }
            float la, ha; unpack2(ya, la, ha);
            float lb, hb; unpack2(yb, lb, hb);
            float dsa = 0.f, dsb = 0.f;
            #pragma unroll
            for (int j = 0; j < NU; j++) {
                float dv = sD[o * NU + j];
                dsa += dv * ua[j];
                dsb += dv * ub[j];
            }
            ypa[(size_t)o * R]      = (la + ha) + dsa;
            ypa[(size_t)o * R + 64] = (lb + hb) + dsb;
        }

        // ---- store X[k] to gmem + packed smem scratch ----
        #pragma unroll
        for (int k = 0; k < 32; k++) {
            float la, ha; unpack2(acc2a[k], la, ha);
            float lb, hb; unpack2(acc2b[k], lb, hb);
            xpa[(size_t)(2 * k) * R]          = la;
            xpa[(size_t)(2 * k + 1) * R]      = ha;
            xpa[(size_t)(2 * k) * R + 64]     = lb;
            xpa[(size_t)(2 * k + 1) * R + 64] = hb;
            xs[k * 128 + tid]      = acc2a[k];
            xs[k * 128 + 64 + tid] = acc2b[k];
        }

        // ---- acc = B u ----
        {
            ull uva = pack2(ua[0], ua[0]);
            ull uvb = pack2(ub[0], ub[0]);
            const ulonglong2* b0 = (const ulonglong2*)(sB2);
            #pragma unroll
            for (int k2 = 0; k2 < 16; k2++) {
                ulonglong2 bb = b0[k2];
                ull z = pack2(0.f, 0.f);
                acc2a[2 * k2 + 0] = fma2(bb.x, uva, z);
                acc2a[2 * k2 + 1] = fma2(bb.y, uva, z);
                acc2b[2 * k2 + 0] = fma2(bb.x, uvb, z);
                acc2b[2 * k2 + 1] = fma2(bb.y, uvb, z);
            }
            #pragma unroll 1
            for (int j = 1; j < NU; j++) {
                ull uaj = pack2(ua[j], ua[j]);
                ull ubj = pack2(ub[j], ub[j]);
                const ulonglong2* bj = (const ulonglong2*)(sB2 + j * 32);
                #pragma unroll
                for (int k2 = 0; k2 < 16; k2++) {
                    ulonglong2 bb = bj[k2];
                    acc2a[2 * k2 + 0] = fma2(bb.x, uaj, acc2a[2 * k2 + 0]);
                    acc2a[2 * k2 + 1] = fma2(bb.y, uaj, acc2a[2 * k2 + 1]);
                    acc2b[2 * k2 + 0] = fma2(bb.x, ubj, acc2b[2 * k2 + 0]);
                    acc2b[2 * k2 + 1] = fma2(bb.y, ubj, acc2b[2 * k2 + 1]);
                }
            }
        }

        // ---- acc += A x_k : per j-pair, 2 x-loads feed 128 fma2 ----
        #pragma unroll 1
        for (int j2 = 0; j2 < 32; j2++) {
            ull pa = xs[j2 * 128 + tid];
            ull pb = xs[j2 * 128 + 64 + tid];
            float xa0, xa1; unpack2(pa, xa0, xa1);
            float xb0, xb1; unpack2(pb, xb0, xb1);
            ull sa0 = pack2(xa0, xa0), sa1 = pack2(xa1, xa1);
            ull sb0 = pack2(xb0, xb0), sb1 = pack2(xb1, xb1);
            const ulonglong2* A0 = (const ulonglong2*)(sA2 + (2 * j2) * 32);
            const ulonglong2* A1 = (const ulonglong2*)(sA2 + (2 * j2 + 1) * 32);
            #pragma unroll
            for (int k2 = 0; k2 < 16; k2++) {
                ulonglong2 aa = A0[k2];
                acc2a[2 * k2 + 0] = fma2(aa.x, sa0, acc2a[2 * k2 + 0]);
                acc2a[2 * k2 + 1] = fma2(aa.y, sa0, acc2a[2 * k2 + 1]);
                acc2b[2 * k2 + 0] = fma2(aa.x, sb0, acc2b[2 * k2 + 0]);
                acc2b[2 * k2 + 1] = fma2(aa.y, sb0, acc2b[2 * k2 + 1]);
                ulonglong2 ab = A1[k2];
                acc2a[2 * k2 + 0] = fma2(ab.x, sa1, acc2a[2 * k2 + 0]);
                acc2a[2 * k2 + 1] = fma2(ab.y, sa1, acc2a[2 * k2 + 1]);
                acc2b[2 * k2 + 0] = fma2(ab.x, sb1, acc2b[2 * k2 + 0]);
                acc2b[2 * k2 + 1] = fma2(ab.y, sb1, acc2b[2 * k2 + 1]);
            }
        }

        upa += (size_t)NU * R;
        ypa += (size_t)NY * R;
        xpa += (size_t)NX * R;
    }
}

#define SMEM_P3 (32768 + 16384 + 2048 + 2048 + 256)

// ---------------------------------------------------------------------------
extern "C" void kernel_launch(void* const* d_in, const int* in_sizes, int n_in,
                              void* d_out, int out_size) {
    const float* u  = (const float*)d_in[0];
    const float* x0 = (const float*)d_in[1];
    const float* A  = (const float*)d_in[2];
    const float* B  = (const float*)d_in[3];
    const float* Cy = (const float*)d_in[4];
    const float* D  = (const float*)d_in[5];
    float* outY = (float*)d_out;
    float* outX = (float*)d_out + (size_t)N_STEPS * NY * R;

    cudaFuncSetAttribute(k_phase3, cudaFuncAttributeMaxDynamicSharedMemorySize, SMEM_P3);

    k_precompute<<<1, 512>>>(A, B);
    k_phase1<<<dim3(C_CHUNKS, R / 64), 256>>>(u);
    k_phase2<<<R / RSUB, NX * RSUB>>>(x0);
    k_phase3<<<dim3(C_CHUNKS, 2), 64, SMEM_P3>>>(u, A, B, Cy, D, outY, outX);
}